// round 3
// baseline (speedup 1.0000x reference)
#include <cuda_runtime.h>
#include <math_constants.h>

#define Bb 4
#define Pp 8192
#define Cc 64
#define Mm 2048
#define NB 64
#define OUTC 384

// scratch (allocation-free rule: __device__ globals)
__device__ int   g_nn_idx[Bb*Mm*NB];
__device__ float g_nn_d2 [Bb*Mm*NB];

// ---------------------------------------------------------------------------
// Kernel 1: farthest point sampling, one block per batch.
// Matches JAX scan exactly: idx[0]=0; mind=1e30; each step update mind with
// dist to previous pick, argmax(mind) -> next (ties: first index).
// Distances with rn ops, no fma contraction, ((dx^2+dy^2)+dz^2).
// ---------------------------------------------------------------------------
__global__ void __launch_bounds__(1024) fps_kernel(const float* __restrict__ pos,
                                                   float* __restrict__ pos_s)
{
    const int b = blockIdx.x;
    const float* pb = pos + (size_t)b * Pp * 3;
    float* ps = pos_s + (size_t)b * Mm * 3;
    const int tid = threadIdx.x;

    float px[8], py[8], pz[8], mind[8];
#pragma unroll
    for (int i = 0; i < 8; i++) {
        int p = tid + i * 1024;
        px[i] = pb[3 * p];
        py[i] = pb[3 * p + 1];
        pz[i] = pb[3 * p + 2];
        mind[i] = 1e30f;
    }

    __shared__ float swv[32];
    __shared__ int   swi[32];
    __shared__ int   s_sel;

    int last = 0;
    for (int t = 0; t < Mm; t++) {
        float lx = pb[3 * last], ly = pb[3 * last + 1], lz = pb[3 * last + 2];
        if (tid == 0) { ps[3 * t] = lx; ps[3 * t + 1] = ly; ps[3 * t + 2] = lz; }

        float bv = -1.0f; int bi = 0;
#pragma unroll
        for (int i = 0; i < 8; i++) {
            float dx = __fsub_rn(px[i], lx);
            float dy = __fsub_rn(py[i], ly);
            float dz = __fsub_rn(pz[i], lz);
            float d  = __fadd_rn(__fadd_rn(__fmul_rn(dx, dx), __fmul_rn(dy, dy)),
                                 __fmul_rn(dz, dz));
            float mval = fminf(mind[i], d);
            mind[i] = mval;
            if (mval > bv) { bv = mval; bi = tid + i * 1024; }  // ascending p -> first idx on tie
        }
#pragma unroll
        for (int o = 16; o > 0; o >>= 1) {
            float ov = __shfl_down_sync(0xffffffffu, bv, o);
            int   oi = __shfl_down_sync(0xffffffffu, bi, o);
            if (ov > bv || (ov == bv && oi < bi)) { bv = ov; bi = oi; }
        }
        if ((tid & 31) == 0) { swv[tid >> 5] = bv; swi[tid >> 5] = bi; }
        __syncthreads();
        if (tid < 32) {
            bv = swv[tid]; bi = swi[tid];
#pragma unroll
            for (int o = 16; o > 0; o >>= 1) {
                float ov = __shfl_down_sync(0xffffffffu, bv, o);
                int   oi = __shfl_down_sync(0xffffffffu, bi, o);
                if (ov > bv || (ov == bv && oi < bi)) { bv = ov; bi = oi; }
            }
            if (tid == 0) s_sel = bi;
        }
        __syncthreads();
        last = s_sel;
    }
}

// ---------------------------------------------------------------------------
// Kernel 2: 64 nearest neighbors per centroid, sorted ascending (tie: lower
// index), matching lax.top_k(-d2, K). One block (128 thr) per centroid;
// d2 for all P points in smem, then 64 successive block argmins.
// ---------------------------------------------------------------------------
__global__ void __launch_bounds__(128) knn_kernel(const float* __restrict__ pos,
                                                  const float* __restrict__ pos_s)
{
    __shared__ float sd[Pp];           // 32 KB
    const int b = blockIdx.y, m = blockIdx.x, tid = threadIdx.x;
    const int bm = b * Mm + m;
    const float* pb = pos + (size_t)b * Pp * 3;
    const float cx = pos_s[bm * 3], cy = pos_s[bm * 3 + 1], cz = pos_s[bm * 3 + 2];

#pragma unroll 4
    for (int i = 0; i < 64; i++) {
        int p = tid + i * 128;
        float dx = __fsub_rn(cx, pb[3 * p]);
        float dy = __fsub_rn(cy, pb[3 * p + 1]);
        float dz = __fsub_rn(cz, pb[3 * p + 2]);
        sd[p] = __fadd_rn(__fadd_rn(__fmul_rn(dx, dx), __fmul_rn(dy, dy)),
                          __fmul_rn(dz, dz));
    }
    __syncthreads();

    float lv = CUDART_INF_F; int li = Pp;
#pragma unroll 4
    for (int i = 0; i < 64; i++) {
        int p = tid + i * 128;
        float v = sd[p];
        if (v < lv) { lv = v; li = p; }
    }

    __shared__ float swv[4];
    __shared__ int   swi[4];
    __shared__ int   sgi;

    for (int r = 0; r < NB; r++) {
        float v = lv; int ix = li;
#pragma unroll
        for (int o = 16; o > 0; o >>= 1) {
            float ov = __shfl_down_sync(0xffffffffu, v, o);
            int   oi = __shfl_down_sync(0xffffffffu, ix, o);
            if (ov < v || (ov == v && oi < ix)) { v = ov; ix = oi; }
        }
        if ((tid & 31) == 0) { swv[tid >> 5] = v; swi[tid >> 5] = ix; }
        __syncthreads();
        if (tid == 0) {
            float gv = swv[0]; int gi = swi[0];
#pragma unroll
            for (int w = 1; w < 4; w++)
                if (swv[w] < gv || (swv[w] == gv && swi[w] < gi)) { gv = swv[w]; gi = swi[w]; }
            sgi = gi;
            g_nn_idx[bm * NB + r] = gi;
            g_nn_d2 [bm * NB + r] = gv;
        }
        __syncthreads();
        int sel = sgi;
        if ((sel & 127) == tid) {                    // owner: remove + rescan local
            sd[sel] = CUDART_INF_F;
            lv = CUDART_INF_F; li = Pp;
#pragma unroll 4
            for (int i = 0; i < 64; i++) {
                int p = tid + i * 128;
                float v2 = sd[p];
                if (v2 < lv) { lv = v2; li = p; }
            }
        }
    }
}

// ---------------------------------------------------------------------------
// Kernel 3: per-centroid MLP for both branches.
// hT[67][k] in smem (stride 68), register-tiled fp32 GEMMs with float4 loads,
// fused bias+relu, masked max over neighbors.
// Block 256 = (tx 32, ty 8).
// ---------------------------------------------------------------------------
#define HT_STRIDE 68

template<int K, int H1, int H2>
__device__ __forceinline__ void run_branch(
    const float* __restrict__ hT, float* __restrict__ h1T, float* __restrict__ red,
    const float* __restrict__ sd2,
    const float* __restrict__ W1, const float* __restrict__ B1b,
    const float* __restrict__ W2, const float* __restrict__ B2b,
    float* __restrict__ outrow, float r2, int tx, int ty, int tid)
{
    constexpr int KV = K / 8;     // neighbors per thread (v)
    constexpr int IU = H1 / 32;   // hidden1 per thread (u)
    constexpr int JU = H2 / 32;   // hidden2 per thread (u)

    // ---- GEMM1: h1T[i][k] = relu(sum_c hT[c][k]*W1[c][i] + b1[i]) ----
    {
        float acc[KV][IU];
#pragma unroll
        for (int v = 0; v < KV; v++)
#pragma unroll
            for (int u = 0; u < IU; u++) acc[v][u] = 0.f;

        for (int c = 0; c < 67; c++) {
            float a[KV];
            const float4* hp = (const float4*)(hT + c * HT_STRIDE + ty * KV);
#pragma unroll
            for (int q = 0; q < KV / 4; q++) {
                float4 t4 = hp[q];
                a[4*q] = t4.x; a[4*q+1] = t4.y; a[4*q+2] = t4.z; a[4*q+3] = t4.w;
            }
            float bb[IU];
            const float* wp = W1 + c * H1 + tx * IU;
            if constexpr (IU == 4) {
                float4 t4 = *(const float4*)wp;
                bb[0] = t4.x; bb[1] = t4.y; bb[2] = t4.z; bb[3] = t4.w;
            } else {
                float2 t2 = *(const float2*)wp;
                bb[0] = t2.x; bb[1] = t2.y;
            }
#pragma unroll
            for (int v = 0; v < KV; v++)
#pragma unroll
                for (int u = 0; u < IU; u++)
                    acc[v][u] = fmaf(a[v], bb[u], acc[v][u]);
        }
        float bias[IU];
#pragma unroll
        for (int u = 0; u < IU; u++) bias[u] = B1b[tx * IU + u];
#pragma unroll
        for (int u = 0; u < IU; u++) {
            int i = tx * IU + u;
#pragma unroll
            for (int v = 0; v < KV; v++) {
                int k = ty * KV + v;
                h1T[i * HT_STRIDE + k] = fmaxf(acc[v][u] + bias[u], 0.f);
            }
        }
    }
    __syncthreads();

    // ---- GEMM2 + masked max over k ----
    {
        float acc[KV][JU];
#pragma unroll
        for (int v = 0; v < KV; v++)
#pragma unroll
            for (int u = 0; u < JU; u++) acc[v][u] = 0.f;

        for (int i = 0; i < H1; i++) {
            float a[KV];
            const float4* hp = (const float4*)(h1T + i * HT_STRIDE + ty * KV);
#pragma unroll
            for (int q = 0; q < KV / 4; q++) {
                float4 t4 = hp[q];
                a[4*q] = t4.x; a[4*q+1] = t4.y; a[4*q+2] = t4.z; a[4*q+3] = t4.w;
            }
            float bb[JU];
            const float4* wp = (const float4*)(W2 + i * H2 + tx * JU);
#pragma unroll
            for (int q = 0; q < JU / 4; q++) {
                float4 t4 = wp[q];
                bb[4*q] = t4.x; bb[4*q+1] = t4.y; bb[4*q+2] = t4.z; bb[4*q+3] = t4.w;
            }
#pragma unroll
            for (int v = 0; v < KV; v++)
#pragma unroll
                for (int u = 0; u < JU; u++)
                    acc[v][u] = fmaf(a[v], bb[u], acc[v][u]);
        }

        float b2[JU];
#pragma unroll
        for (int u = 0; u < JU; u++) b2[u] = B2b[tx * JU + u];
        float mx[JU];
#pragma unroll
        for (int u = 0; u < JU; u++) mx[u] = -1e30f;
#pragma unroll
        for (int v = 0; v < KV; v++) {
            bool ok = (sd2[ty * KV + v] <= r2);
#pragma unroll
            for (int u = 0; u < JU; u++) {
                float val = fmaxf(acc[v][u] + b2[u], 0.f);
                if (!ok) val = -1e30f;
                mx[u] = fmaxf(mx[u], val);
            }
        }
#pragma unroll
        for (int u = 0; u < JU; u++) red[ty * H2 + tx * JU + u] = mx[u];
        __syncthreads();
        for (int j = tid; j < H2; j += 256) {
            float mm = red[j];
#pragma unroll
            for (int w = 1; w < 8; w++) mm = fmaxf(mm, red[w * H2 + j]);
            outrow[j] = mm;
        }
        __syncthreads();
    }
}

__global__ void __launch_bounds__(256) mlp_kernel(
    const float* __restrict__ x, const float* __restrict__ pos,
    const float* __restrict__ pos_s,
    const float* __restrict__ w1_0, const float* __restrict__ b1_0,
    const float* __restrict__ w1_1, const float* __restrict__ b1_1,
    const float* __restrict__ w2_0, const float* __restrict__ b2_0,
    const float* __restrict__ w2_1, const float* __restrict__ b2_1,
    float* __restrict__ out)
{
    extern __shared__ float sm[];
    float* hT  = sm;                         // 67 * 68 = 4556 floats
    float* h1T = hT + 67 * HT_STRIDE;        // 128 * 68 = 8704 floats
    float* red = h1T + 128 * HT_STRIDE;      // 8 * 256 = 2048 floats
    float* sd2 = red + 2048;                 // 64
    float* sps = sd2 + 64;                   // 4
    int*   snn = (int*)(sps + 4);            // 64

    const int b = blockIdx.y, m = blockIdx.x, tid = threadIdx.x;
    const int tx = tid & 31, ty = tid >> 5;
    const int bm = b * Mm + m;

    if (tid < NB) {
        snn[tid] = g_nn_idx[bm * NB + tid];
        sd2[tid] = g_nn_d2 [bm * NB + tid];
    }
    if (tid < 3) sps[tid] = pos_s[bm * 3 + tid];
    __syncthreads();

    // gather features (transposed): hT[c][k]
    for (int t = tid; t < NB * Cc; t += 256) {
        int k = t >> 6, c = t & 63;
        hT[c * HT_STRIDE + k] = x[((size_t)(b * Pp) + snn[k]) * Cc + c];
    }
    // relative positions: hT[64+d][k]
    for (int t = tid; t < NB * 3; t += 256) {
        int k = t / 3, d = t - 3 * k;
        hT[(64 + d) * HT_STRIDE + k] =
            __fsub_rn(pos[((size_t)(b * Pp) + snn[k]) * 3 + d], sps[d]);
    }
    __syncthreads();

    const float R2A = (float)(0.2 * 0.2);   // branch 1 radius^2 (JAX-equivalent cast)
    const float R2B = (float)(0.4 * 0.4);   // branch 2 radius^2

    float* outrow = out + (size_t)bm * OUTC;
    // branch 2: K=64, 67->128->256, output channels [128,384)
    run_branch<64, 128, 256>(hT, h1T, red, sd2, w2_0, b2_0, w2_1, b2_1,
                             outrow + 128, R2B, tx, ty, tid);
    // branch 1: K=32 (prefix of sorted 64-NN), 67->64->128, channels [0,128)
    run_branch<32, 64, 128>(hT, h1T, red, sd2, w1_0, b1_0, w1_1, b1_1,
                            outrow, R2A, tx, ty, tid);
}

// ---------------------------------------------------------------------------
// launch
// ---------------------------------------------------------------------------
extern "C" void kernel_launch(void* const* d_in, const int* in_sizes, int n_in,
                              void* d_out, int out_size)
{
    const float* x    = (const float*)d_in[0];
    const float* pos  = (const float*)d_in[1];
    const float* w1_0 = (const float*)d_in[2];
    const float* b1_0 = (const float*)d_in[3];
    const float* w1_1 = (const float*)d_in[4];
    const float* b1_1 = (const float*)d_in[5];
    const float* w2_0 = (const float*)d_in[6];
    const float* b2_0 = (const float*)d_in[7];
    const float* w2_1 = (const float*)d_in[8];
    const float* b2_1 = (const float*)d_in[9];

    float* out   = (float*)d_out;
    float* pos_s = out + (size_t)Bb * Mm * OUTC;   // [out | pos_s] layout

    const int mlp_smem = (67 * HT_STRIDE + 128 * HT_STRIDE + 2048 + 64 + 4 + 64) * 4;
    cudaFuncSetAttribute(mlp_kernel, cudaFuncAttributeMaxDynamicSharedMemorySize, mlp_smem);

    fps_kernel<<<Bb, 1024>>>(pos, pos_s);

    dim3 g(Mm, Bb);
    knn_kernel<<<g, 128>>>(pos, pos_s);

    mlp_kernel<<<g, 256, mlp_smem>>>(x, pos, pos_s,
                                     w1_0, b1_0, w1_1, b1_1,
                                     w2_0, b2_0, w2_1, b2_1, out);
}

// round 4
// speedup vs baseline: 1.5493x; 1.5493x over previous
#include <cuda_runtime.h>
#include <math_constants.h>

#define Bb 4
#define Pp 8192
#define Cc 64
#define Mm 2048
#define NB 64
#define OUTC 384

// scratch (allocation-free rule: __device__ globals)
__device__ int   g_nn_idx[Bb*Mm*NB];
__device__ float g_nn_d2 [Bb*Mm*NB];

// ---------------- packed f32x2 helpers (bitwise == two scalar rn ops) -------
typedef unsigned long long u64;

__device__ __forceinline__ u64 pk2(float lo, float hi) {
    u64 r; asm("mov.b64 %0, {%1, %2};" : "=l"(r) : "f"(lo), "f"(hi)); return r;
}
__device__ __forceinline__ void upk2(float& lo, float& hi, u64 v) {
    asm("mov.b64 {%0, %1}, %2;" : "=f"(lo), "=f"(hi) : "l"(v));
}
__device__ __forceinline__ u64 add2(u64 a, u64 b) {
    u64 d; asm("add.rn.f32x2 %0, %1, %2;" : "=l"(d) : "l"(a), "l"(b)); return d;
}
__device__ __forceinline__ u64 mul2(u64 a, u64 b) {
    u64 d; asm("mul.rn.f32x2 %0, %1, %2;" : "=l"(d) : "l"(a), "l"(b)); return d;
}
__device__ __forceinline__ u64 fma2(u64 a, u64 b, u64 c) {
    u64 d; asm("fma.rn.f32x2 %0, %1, %2, %3;" : "=l"(d) : "l"(a), "l"(b), "l"(c)); return d;
}

// ---------------------------------------------------------------------------
// Kernel 1: farthest point sampling, one block per batch (throughput-bound).
// d computed with packed rn ops, identical rounding to reference lowering:
// ((dx*dx + dy*dy) + dz*dz), no fma contraction. min/max on uint bits (ALU
// pipe, order-preserving for non-negative floats). REDUX for reductions,
// index resolved by deferred equality scan (lowest index wins ties).
// ---------------------------------------------------------------------------
__global__ void __launch_bounds__(1024) fps_kernel(const float* __restrict__ pos,
                                                   float* __restrict__ pos_s)
{
    const int b = blockIdx.x;
    const float* pb = pos + (size_t)b * Pp * 3;
    float* ps = pos_s + (size_t)b * Mm * 3;
    const int tid = threadIdx.x;

    u64 px2[4], py2[4], pz2[4];
    unsigned mind[8];
#pragma unroll
    for (int q = 0; q < 4; q++) {
        int p0 = tid + (2 * q) * 1024;
        int p1 = tid + (2 * q + 1) * 1024;
        px2[q] = pk2(pb[3 * p0],     pb[3 * p1]);
        py2[q] = pk2(pb[3 * p0 + 1], pb[3 * p1 + 1]);
        pz2[q] = pk2(pb[3 * p0 + 2], pb[3 * p1 + 2]);
    }
#pragma unroll
    for (int i = 0; i < 8; i++) mind[i] = __float_as_uint(1e30f);

    __shared__ unsigned swv[32];
    __shared__ unsigned swi[32];
    __shared__ unsigned s_sel;

    int last = 0;
    for (int t = 0; t < Mm; t++) {
        float lx = pb[3 * last], ly = pb[3 * last + 1], lz = pb[3 * last + 2];
        if (tid == 0) { ps[3 * t] = lx; ps[3 * t + 1] = ly; ps[3 * t + 2] = lz; }

        u64 nx2 = pk2(-lx, -lx);
        u64 ny2 = pk2(-ly, -ly);
        u64 nz2 = pk2(-lz, -lz);

        unsigned bv = 0u;
#pragma unroll
        for (int q = 0; q < 4; q++) {
            u64 dx = add2(px2[q], nx2);
            u64 dy = add2(py2[q], ny2);
            u64 dz = add2(pz2[q], nz2);
            u64 s  = add2(add2(mul2(dx, dx), mul2(dy, dy)), mul2(dz, dz));
            float dlo, dhi;
            upk2(dlo, dhi, s);
            unsigned m0 = min(mind[2 * q],     __float_as_uint(dlo));
            unsigned m1 = min(mind[2 * q + 1], __float_as_uint(dhi));
            mind[2 * q]     = m0;
            mind[2 * q + 1] = m1;
            bv = max(bv, max(m0, m1));
        }

        // warp argmax (value first, then lowest index among matches)
        unsigned wv = __reduce_max_sync(0xffffffffu, bv);
        unsigned cand = 0xffffffffu;
        if (bv == wv) {
#pragma unroll
            for (int i = 7; i >= 0; i--)
                if (mind[i] == wv) cand = (unsigned)(tid + (i << 10));
        }
        unsigned wi = __reduce_min_sync(0xffffffffu, cand);
        if ((tid & 31) == 0) { swv[tid >> 5] = wv; swi[tid >> 5] = wi; }
        __syncthreads();
        if (tid < 32) {
            unsigned v = swv[tid], ii = swi[tid];
            unsigned gv = __reduce_max_sync(0xffffffffu, v);
            unsigned c2 = (v == gv) ? ii : 0xffffffffu;
            unsigned gi = __reduce_min_sync(0xffffffffu, c2);
            if (tid == 0) s_sel = gi;
        }
        __syncthreads();
        last = (int)s_sel;
    }
}

// ---------------------------------------------------------------------------
// Kernel 2: 64 nearest neighbors per centroid, sorted ascending (tie: lower
// index). One block (128 thr) per centroid; d2 in smem; 64 rounds of block
// argmin via REDUX; cooperative warp rescan for the owner thread.
// ---------------------------------------------------------------------------
__global__ void __launch_bounds__(128) knn_kernel(const float* __restrict__ pos,
                                                  const float* __restrict__ pos_s)
{
    __shared__ float sd[Pp];           // 32 KB
    const int b = blockIdx.y, m = blockIdx.x, tid = threadIdx.x;
    const int bm = b * Mm + m;
    const float* pb = pos + (size_t)b * Pp * 3;
    const float cx = pos_s[bm * 3], cy = pos_s[bm * 3 + 1], cz = pos_s[bm * 3 + 2];

#pragma unroll 4
    for (int i = 0; i < 64; i++) {
        int p = tid + i * 128;
        float dx = __fsub_rn(cx, pb[3 * p]);
        float dy = __fsub_rn(cy, pb[3 * p + 1]);
        float dz = __fsub_rn(cz, pb[3 * p + 2]);
        sd[p] = __fadd_rn(__fadd_rn(__fmul_rn(dx, dx), __fmul_rn(dy, dy)),
                          __fmul_rn(dz, dz));
    }
    __syncthreads();

    unsigned lv = 0x7f800000u;   // +inf bits
    unsigned li = 0xffffffffu;
#pragma unroll 4
    for (int i = 0; i < 64; i++) {
        int p = tid + i * 128;
        unsigned v = __float_as_uint(sd[p]);   // d2 >= 0 -> bit order == numeric
        if (v < lv) { lv = v; li = (unsigned)p; }
    }

    __shared__ unsigned swv[4];
    __shared__ unsigned swi[4];
    __shared__ unsigned sgi;

    const unsigned wid = tid >> 5;

    for (int r = 0; r < NB; r++) {
        unsigned wv = __reduce_min_sync(0xffffffffu, lv);
        unsigned cand = (lv == wv) ? li : 0xffffffffu;
        unsigned wi = __reduce_min_sync(0xffffffffu, cand);
        if ((tid & 31) == 0) { swv[wid] = wv; swi[wid] = wi; }
        __syncthreads();
        if (tid == 0) {
            unsigned gv = swv[0], gi = swi[0];
#pragma unroll
            for (int w = 1; w < 4; w++)
                if (swv[w] < gv || (swv[w] == gv && swi[w] < gi)) { gv = swv[w]; gi = swi[w]; }
            sgi = gi;
            g_nn_idx[bm * NB + r] = (int)gi;
            g_nn_d2 [bm * NB + r] = __uint_as_float(gv);
        }
        __syncthreads();
        unsigned sel = sgi;
        unsigned ot = sel & 127u;          // owner thread within block
        if (wid == (ot >> 5)) {            // owner warp: cooperative rescan
            if (tid == (int)ot) sd[sel] = CUDART_INF_F;
            __syncwarp();
            int lane = tid & 31;
            unsigned v0 = __float_as_uint(sd[ot + (unsigned)(2 * lane) * 128u]);
            unsigned v1 = __float_as_uint(sd[ot + (unsigned)(2 * lane + 1) * 128u]);
            unsigned mv = min(v0, v1);
            unsigned mi = (v0 <= v1) ? (ot + (unsigned)(2 * lane) * 128u)
                                     : (ot + (unsigned)(2 * lane + 1) * 128u);
            unsigned rv = __reduce_min_sync(0xffffffffu, mv);
            unsigned rc = (mv == rv) ? mi : 0xffffffffu;
            unsigned ri = __reduce_min_sync(0xffffffffu, rc);
            if (tid == (int)ot) { lv = rv; li = ri; }
        }
    }
}

// ---------------------------------------------------------------------------
// Kernel 3: per-centroid MLP for both branches, packed f32x2 FMAs.
// Block 256 = (tx 32, ty 8).
// ---------------------------------------------------------------------------
#define HT_STRIDE 68

template<int K, int H1, int H2>
__device__ __forceinline__ void run_branch(
    const float* __restrict__ hT, float* __restrict__ h1T, float* __restrict__ red,
    const float* __restrict__ sd2,
    const float* __restrict__ W1, const float* __restrict__ B1b,
    const float* __restrict__ W2, const float* __restrict__ B2b,
    float* __restrict__ outrow, float r2, int tx, int ty, int tid)
{
    constexpr int KV = K / 8;     // neighbors per thread
    constexpr int IU = H1 / 32;   // hidden1 channels per thread
    constexpr int JU = H2 / 32;   // hidden2 channels per thread
    constexpr int IU2 = IU / 2, JU2 = JU / 2;

    // ---- GEMM1: h1[i][k] = relu(sum_c hT[c][k]*W1[c][i] + b1[i]) ----
    {
        u64 acc[KV][IU2];
#pragma unroll
        for (int v = 0; v < KV; v++)
#pragma unroll
            for (int u = 0; u < IU2; u++) acc[v][u] = 0ull;

        for (int c = 0; c < 67; c++) {
            float a[KV];
            const float4* hp = (const float4*)(hT + c * HT_STRIDE + ty * KV);
#pragma unroll
            for (int q = 0; q < KV / 4; q++) {
                float4 t4 = hp[q];
                a[4*q] = t4.x; a[4*q+1] = t4.y; a[4*q+2] = t4.z; a[4*q+3] = t4.w;
            }
            u64 aa[KV];
#pragma unroll
            for (int v = 0; v < KV; v++) aa[v] = pk2(a[v], a[v]);

            u64 bb[IU2];
            const float* wp = W1 + c * H1 + tx * IU;
            if constexpr (IU == 4) {
                float4 t4 = *(const float4*)wp;
                bb[0] = pk2(t4.x, t4.y); bb[1] = pk2(t4.z, t4.w);
            } else {
                float2 t2 = *(const float2*)wp;
                bb[0] = pk2(t2.x, t2.y);
            }
#pragma unroll
            for (int v = 0; v < KV; v++)
#pragma unroll
                for (int u = 0; u < IU2; u++)
                    acc[v][u] = fma2(aa[v], bb[u], acc[v][u]);
        }
        float bias[IU];
#pragma unroll
        for (int u = 0; u < IU; u++) bias[u] = B1b[tx * IU + u];
#pragma unroll
        for (int u = 0; u < IU2; u++) {
#pragma unroll
            for (int v = 0; v < KV; v++) {
                float lo, hi;
                upk2(lo, hi, acc[v][u]);
                int i0 = tx * IU + 2 * u;
                int k  = ty * KV + v;
                h1T[i0 * HT_STRIDE + k]       = fmaxf(lo + bias[2*u],     0.f);
                h1T[(i0 + 1) * HT_STRIDE + k] = fmaxf(hi + bias[2*u + 1], 0.f);
            }
        }
    }
    __syncthreads();

    // ---- GEMM2 + masked max over k ----
    {
        u64 acc[KV][JU2];
#pragma unroll
        for (int v = 0; v < KV; v++)
#pragma unroll
            for (int u = 0; u < JU2; u++) acc[v][u] = 0ull;

        for (int i = 0; i < H1; i++) {
            float a[KV];
            const float4* hp = (const float4*)(h1T + i * HT_STRIDE + ty * KV);
#pragma unroll
            for (int q = 0; q < KV / 4; q++) {
                float4 t4 = hp[q];
                a[4*q] = t4.x; a[4*q+1] = t4.y; a[4*q+2] = t4.z; a[4*q+3] = t4.w;
            }
            u64 aa[KV];
#pragma unroll
            for (int v = 0; v < KV; v++) aa[v] = pk2(a[v], a[v]);

            u64 bb[JU2];
            const float4* wp = (const float4*)(W2 + i * H2 + tx * JU);
#pragma unroll
            for (int q = 0; q < JU / 4; q++) {
                float4 t4 = wp[q];
                bb[2*q]   = pk2(t4.x, t4.y);
                bb[2*q+1] = pk2(t4.z, t4.w);
            }
#pragma unroll
            for (int v = 0; v < KV; v++)
#pragma unroll
                for (int u = 0; u < JU2; u++)
                    acc[v][u] = fma2(aa[v], bb[u], acc[v][u]);
        }

        float b2[JU];
#pragma unroll
        for (int u = 0; u < JU; u++) b2[u] = B2b[tx * JU + u];
        float mx[JU];
#pragma unroll
        for (int u = 0; u < JU; u++) mx[u] = -1e30f;
#pragma unroll
        for (int v = 0; v < KV; v++) {
            bool ok = (sd2[ty * KV + v] <= r2);
#pragma unroll
            for (int u = 0; u < JU2; u++) {
                float lo, hi;
                upk2(lo, hi, acc[v][u]);
                float v0 = fmaxf(lo + b2[2*u],     0.f);
                float v1 = fmaxf(hi + b2[2*u + 1], 0.f);
                if (!ok) { v0 = -1e30f; v1 = -1e30f; }
                mx[2*u]     = fmaxf(mx[2*u],     v0);
                mx[2*u + 1] = fmaxf(mx[2*u + 1], v1);
            }
        }
#pragma unroll
        for (int u = 0; u < JU; u++) red[ty * H2 + tx * JU + u] = mx[u];
        __syncthreads();
        for (int j = tid; j < H2; j += 256) {
            float mm = red[j];
#pragma unroll
            for (int w = 1; w < 8; w++) mm = fmaxf(mm, red[w * H2 + j]);
            outrow[j] = mm;
        }
        __syncthreads();
    }
}

__global__ void __launch_bounds__(256) mlp_kernel(
    const float* __restrict__ x, const float* __restrict__ pos,
    const float* __restrict__ pos_s,
    const float* __restrict__ w1_0, const float* __restrict__ b1_0,
    const float* __restrict__ w1_1, const float* __restrict__ b1_1,
    const float* __restrict__ w2_0, const float* __restrict__ b2_0,
    const float* __restrict__ w2_1, const float* __restrict__ b2_1,
    float* __restrict__ out)
{
    extern __shared__ float sm[];
    float* hT  = sm;                         // 67 * 68 = 4556 floats
    float* h1T = hT + 67 * HT_STRIDE;        // 128 * 68 = 8704 floats
    float* red = h1T + 128 * HT_STRIDE;      // 8 * 256 = 2048 floats
    float* sd2 = red + 2048;                 // 64
    float* sps = sd2 + 64;                   // 4
    int*   snn = (int*)(sps + 4);            // 64

    const int b = blockIdx.y, m = blockIdx.x, tid = threadIdx.x;
    const int tx = tid & 31, ty = tid >> 5;
    const int bm = b * Mm + m;

    if (tid < NB) {
        snn[tid] = g_nn_idx[bm * NB + tid];
        sd2[tid] = g_nn_d2 [bm * NB + tid];
    }
    if (tid < 3) sps[tid] = pos_s[bm * 3 + tid];
    __syncthreads();

    // gather features (transposed): hT[c][k]
    for (int t = tid; t < NB * Cc; t += 256) {
        int k = t >> 6, c = t & 63;
        hT[c * HT_STRIDE + k] = x[((size_t)(b * Pp) + snn[k]) * Cc + c];
    }
    // relative positions: hT[64+d][k]
    for (int t = tid; t < NB * 3; t += 256) {
        int k = t / 3, d = t - 3 * k;
        hT[(64 + d) * HT_STRIDE + k] =
            __fsub_rn(pos[((size_t)(b * Pp) + snn[k]) * 3 + d], sps[d]);
    }
    __syncthreads();

    const float R2A = (float)(0.2 * 0.2);
    const float R2B = (float)(0.4 * 0.4);

    float* outrow = out + (size_t)bm * OUTC;
    // branch 2: K=64, 67->128->256, output channels [128,384)
    run_branch<64, 128, 256>(hT, h1T, red, sd2, w2_0, b2_0, w2_1, b2_1,
                             outrow + 128, R2B, tx, ty, tid);
    // branch 1: K=32 (prefix of sorted 64-NN), 67->64->128, channels [0,128)
    run_branch<32, 64, 128>(hT, h1T, red, sd2, w1_0, b1_0, w1_1, b1_1,
                            outrow, R2A, tx, ty, tid);
}

// ---------------------------------------------------------------------------
// launch
// ---------------------------------------------------------------------------
extern "C" void kernel_launch(void* const* d_in, const int* in_sizes, int n_in,
                              void* d_out, int out_size)
{
    const float* x    = (const float*)d_in[0];
    const float* pos  = (const float*)d_in[1];
    const float* w1_0 = (const float*)d_in[2];
    const float* b1_0 = (const float*)d_in[3];
    const float* w1_1 = (const float*)d_in[4];
    const float* b1_1 = (const float*)d_in[5];
    const float* w2_0 = (const float*)d_in[6];
    const float* b2_0 = (const float*)d_in[7];
    const float* w2_1 = (const float*)d_in[8];
    const float* b2_1 = (const float*)d_in[9];

    float* out   = (float*)d_out;
    float* pos_s = out + (size_t)Bb * Mm * OUTC;   // [out | pos_s] layout

    const int mlp_smem = (67 * HT_STRIDE + 128 * HT_STRIDE + 2048 + 64 + 4 + 64) * 4;
    cudaFuncSetAttribute(mlp_kernel, cudaFuncAttributeMaxDynamicSharedMemorySize, mlp_smem);

    fps_kernel<<<Bb, 1024>>>(pos, pos_s);

    dim3 g(Mm, Bb);
    knn_kernel<<<g, 128>>>(pos, pos_s);

    mlp_kernel<<<g, 256, mlp_smem>>>(x, pos, pos_s,
                                     w1_0, b1_0, w1_1, b1_1,
                                     w2_0, b2_0, w2_1, b2_1, out);
}